// round 16
// baseline (speedup 1.0000x reference)
#include <cuda_runtime.h>
#include <cstdint>

typedef unsigned long long ull;

#define NN 512
#define F 16
#define TE 128            // tile edge
#define RDS 36            // per-row duplicated storage stride (floats)
#define CS 132            // sCol stride (floats)
#define MS 132            // sMirH stride (floats)
#define NTHREADS 256

// dynamic smem layout (bytes, 16B aligned). sCol/sNaC overlay the mirror
// half-tile: both are consumed into registers before the first mirror STS.
#define OFF_ROWD 0                         // 128*36*4 = 18432
#define OFF_NARD 18432                     // 256*4    = 1024
#define OFF_MIR  19456                     // 64*132*4 = 33792 (half tile)
#define OFF_COL  19456                     // 16*132*4 = 8448  (overlay)
#define OFF_NAC  27904                     // 132*4    = 528   (overlay)
#define SMEM_TOTAL 53248

struct ull2_t { ull x, y; };

__device__ __forceinline__ ull pack2(float lo, float hi) {
    ull r;
    asm("mov.b64 %0, {%1, %2};" : "=l"(r) : "f"(lo), "f"(hi));
    return r;
}
__device__ __forceinline__ void unpack2(ull v, float& lo, float& hi) {
    asm("mov.b64 {%0, %1}, %2;" : "=f"(lo), "=f"(hi) : "l"(v));
}
__device__ __forceinline__ ull fma2(ull a, ull b, ull c) {
    ull d;
    asm("fma.rn.f32x2 %0, %1, %2, %3;" : "=l"(d) : "l"(a), "l"(b), "l"(c));
    return d;
}
__device__ __forceinline__ ull add2(ull a, ull b) {
    ull d;
    asm("add.rn.f32x2 %0, %1, %2;" : "=l"(d) : "l"(a), "l"(b));
    return d;
}

// exp(-0.1*sqrt(max(v,1e-6))) ; result always in (0,1) so clip is free
__device__ __forceinline__ float gauss1(float v) {
    float t = fmaxf(v, 1e-6f);
    float d;
    asm("sqrt.approx.f32 %0, %1;" : "=f"(d) : "f"(t));
    float xx = d * -0.14426950408889634f;   // -0.1 * log2(e)
    float e;
    asm("ex2.approx.f32 %0, %1;" : "=f"(e) : "f"(xx));
    return e;
}

// mirror swizzle over 64 local rows: bank-clean for both STS.128 phases and
// the transposed 32-lane scalar reads (verified: banks 16(q&1) + (cc^s) + 4d
// are pairwise distinct across the warp's (q, cc) pattern)
__device__ __forceinline__ int msw(int r) { return ((r >> 3) & 7) << 2; }

__global__ void __launch_bounds__(NTHREADS, 3)
npg_sym128(const float* __restrict__ x, const float* __restrict__ msk,
           float* __restrict__ out) {
    extern __shared__ __align__(16) char dsm[];
    float* sRowD = reinterpret_cast<float*>(dsm + OFF_ROWD);
    float* sNaRD = reinterpret_cast<float*>(dsm + OFF_NARD);
    float* sMirH = reinterpret_cast<float*>(dsm + OFF_MIR);
    float* sCol  = reinterpret_cast<float*>(dsm + OFF_COL);
    float* sNaC  = reinterpret_cast<float*>(dsm + OFF_NAC);

    const int tid = threadIdx.x;
    const int bk  = blockIdx.y;

    // upper-triangular pair (ti <= tj) of the 4x4 tile grid (10 pairs)
    int t = blockIdx.x, ti = 0;
    while (t >= 4 - ti) { t -= 4 - ti; ++ti; }
    const int tj = ti + t;
    const int rbase = ti * TE;
    const int cbase = tj * TE;
    const bool mir = (ti != tj);

    // ---- stage A = x*msk (rows duplicated, cols plain) + fused na ----
    const float4* xb = reinterpret_cast<const float4*>(x + (size_t)bk * NN * F);
    const float*  mb = msk + (size_t)bk * NN;
    #pragma unroll
    for (int k = 0; k < 2; k++) {
        int i  = k * NTHREADS + tid;
        int n  = i >> 2;                 // node 0..127
        int fq = i & 3;                  // f quad
        int f0 = fq << 2;

        float4 v = __ldg(&xb[(rbase + n) * 4 + fq]);
        float  m = __ldg(&mb[rbase + n]);
        float r0 = v.x * m, r1 = v.y * m, r2 = v.z * m, r3 = v.w * m;
        ull* rd = reinterpret_cast<ull*>(&sRowD[n * RDS + (f0 << 1)]);
        rd[0] = pack2(r0, r0);
        rd[1] = pack2(r1, r1);
        rd[2] = pack2(r2, r2);
        rd[3] = pack2(r3, r3);
        float s = fmaf(r0, r0, fmaf(r1, r1, fmaf(r2, r2, r3 * r3)));
        s += __shfl_xor_sync(~0u, s, 1);
        s += __shfl_xor_sync(~0u, s, 2);
        if (fq == 0) *reinterpret_cast<ull*>(&sNaRD[2 * n]) = pack2(s, s);

        float4 w  = __ldg(&xb[(cbase + n) * 4 + fq]);
        float  mc = __ldg(&mb[cbase + n]);
        float c0v = w.x * mc, c1v = w.y * mc, c2v = w.z * mc, c3v = w.w * mc;
        sCol[(f0 + 0) * CS + n] = c0v;
        sCol[(f0 + 1) * CS + n] = c1v;
        sCol[(f0 + 2) * CS + n] = c2v;
        sCol[(f0 + 3) * CS + n] = c3v;
        float sc = fmaf(c0v, c0v, fmaf(c1v, c1v, fmaf(c2v, c2v, c3v * c3v)));
        sc += __shfl_xor_sync(~0u, sc, 1);
        sc += __shfl_xor_sync(~0u, sc, 2);
        if (fq == 0) sNaC[n] = sc;
    }
    __syncthreads();

    // thread mapping: lane = cx(4b) | fh(bit4); warp = colhalf(bit2) | ry(2b)
    const int lane = tid & 31;
    const int wid  = tid >> 5;
    const int cx   = lane & 15;
    const int fh   = lane >> 4;          // f-half: 0 -> f[0,8), 1 -> f[8,16)
    const int ry   = wid & 3;            // 4 row groups of 16 rows per phase
    const int ch   = wid >> 2;           // column half
    const int c0   = (ch << 6) + (cx << 2);   // 4 adjacent cols

    // ---- cache 4 cols x 8 f (this lane's f-half): 16 ulls = 32 regs ----
    ull ccA[8], ccB[8];
    #pragma unroll
    for (int j = 0; j < 8; j++) {
        ull2_t u = *reinterpret_cast<const ull2_t*>(&sCol[(fh * 8 + j) * CS + c0]);
        ccA[j] = u.x;
        ccB[j] = u.y;
    }
    ull nacA, nacB;
    {
        float4 q = *reinterpret_cast<const float4*>(&sNaC[c0]);
        nacA = pack2(q.x, q.y);
        nacB = pack2(q.z, q.w);
    }
    __syncthreads();   // sCol/sNaC fully consumed before sMirH is written

    float* outb = out + (size_t)bk * NN * NN;
    const ull NEG2 = pack2(-2.f, -2.f);

    // ---- two phases of 64 rows (half-tile mirror buffer) ----
    #pragma unroll 1
    for (int phase = 0; phase < 2; phase++) {
        const int rloc = (phase << 6) + (ry << 4);      // phase-global row base
        const float* rbp = &sRowD[rloc * RDS + (fh << 4)];
        const ull*   nau = reinterpret_cast<const ull*>(sNaRD) + rloc + fh;
        float* opL = outb + (size_t)(rbase + rloc + fh) * NN + cbase + c0;
        const int lr0 = (ry << 4) + fh;                 // local row in half

        #pragma unroll 2
        for (int i = 0; i < 16; i += 2) {
            ull a0A = 0ULL, a0B = 0ULL, a1A = 0ULL, a1B = 0ULL;
            #pragma unroll
            for (int j = 0; j < 4; j++) {
                ull2_t w0 = *reinterpret_cast<const ull2_t*>(&rbp[i * RDS + 4 * j]);
                ull2_t w1 = *reinterpret_cast<const ull2_t*>(&rbp[(i + 1) * RDS + 4 * j]);
                a0A = fma2(w0.x, ccA[2 * j],     a0A);
                a0B = fma2(w0.x, ccB[2 * j],     a0B);
                a1A = fma2(w1.x, ccA[2 * j],     a1A);
                a1B = fma2(w1.x, ccB[2 * j],     a1B);
                a0A = fma2(w0.y, ccA[2 * j + 1], a0A);
                a0B = fma2(w0.y, ccB[2 * j + 1], a0B);
                a1A = fma2(w1.y, ccA[2 * j + 1], a1A);
                a1B = fma2(w1.y, ccB[2 * j + 1], a1B);
            }

            // combine f-halves: fh0 finalizes row i, fh1 finalizes row i+1
            ull sendA = fh ? a0A : a1A;
            ull sendB = fh ? a0B : a1B;
            ull gotA = __shfl_xor_sync(~0u, sendA, 16);
            ull gotB = __shfl_xor_sync(~0u, sendB, 16);
            ull fullA = add2(fh ? a1A : a0A, gotA);
            ull fullB = add2(fh ? a1B : a0B, gotB);

            ull nar = nau[i];                          // (na_r, na_r) for row i+fh
            ull vA = fma2(fullA, NEG2, add2(nar, nacA));
            ull vB = fma2(fullB, NEG2, add2(nar, nacB));

            float p0, p1, p2, p3;
            unpack2(vA, p0, p1);
            unpack2(vB, p2, p3);
            float4 o;
            o.x = gauss1(p0);
            o.y = gauss1(p1);
            o.z = gauss1(p2);
            o.w = gauss1(p3);

            *reinterpret_cast<float4*>(opL + (size_t)i * NN) = o;   // coalesced
            if (mir) {
                const int lr = lr0 + i;
                *reinterpret_cast<float4*>(&sMirH[lr * MS + (c0 ^ msw(lr))]) = o;
            }
        }

        // ---- mirror write-out of this 64-row half (transposed, coalesced) ----
        if (mir) {
            __syncthreads();   // half resident in sMirH
            #pragma unroll
            for (int it = 0; it < 8; it++) {
                int idx = it * NTHREADS + tid;   // 0..2047
                int q   = idx & 15;              // row quad 0..15 (64 rows)
                int cc  = idx >> 4;              // mirror row 0..127
                int s   = ((q >> 1) & 7) << 2;   // = msw(4q)
                int r0  = 4 * q;
                float4 w;                        // 32 distinct banks per warp
                w.x = sMirH[(r0 + 0) * MS + (cc ^ s)];
                w.y = sMirH[(r0 + 1) * MS + (cc ^ s)];
                w.z = sMirH[(r0 + 2) * MS + (cc ^ s)];
                w.w = sMirH[(r0 + 3) * MS + (cc ^ s)];
                *reinterpret_cast<float4*>(
                    &outb[(size_t)(cbase + cc) * NN + rbase + (phase << 6) + r0]) = w;
            }
            if (phase == 0) __syncthreads();   // protect sMirH before phase-1 STS
        }
    }
}

extern "C" void kernel_launch(void* const* d_in, const int* in_sizes, int n_in,
                              void* d_out, int out_size) {
    const float* x   = (const float*)d_in[0];   // (8,64,512,16)
    const float* msk = (const float*)d_in[1];   // (8,64,512,1)
    float* out = (float*)d_out;                 // (8,64,512,512,1)

    cudaFuncSetAttribute(npg_sym128,
                         cudaFuncAttributeMaxDynamicSharedMemorySize, SMEM_TOTAL);

    int bk_total = in_sizes[0] / (NN * F);      // 512
    dim3 grid(10, bk_total);                    // 10 upper-tri 128-tiles x 512 bins
    npg_sym128<<<grid, NTHREADS, SMEM_TOTAL>>>(x, msk, out);
}